// round 3
// baseline (speedup 1.0000x reference)
#include <cuda_runtime.h>
#include <cuda_bf16.h>

// GCN layer:  out = segment_sum_{src}( norm[src]*w*norm[dst] * (features@K)[dst] ) + bias
// Algebra: norm[src] factors out of the per-src sum. Pipeline:
//   1) deg histogram (atomics)
//   2) h' = (features @ K) * rsqrt(max(deg,1))   (store norm too)
//   3) edge scatter: out[src] += ew * h'[dst]    (red.global.add.v4.f32)
//   4) out = out * norm + bias
//
// Inputs (metadata order): features f32[100000,32], edge_srcs i32[E],
// edge_dsts i32[E], edge_weights f32[E], kernels f32[32,32], biases f32[32].
// Output f32[100000,32].

#define NUM_NODES 100000
#define F 32

// Scratch (static __device__ — no allocations allowed)
__device__ __align__(16) float g_h[NUM_NODES * F];   // h' = norm * (features @ K)
__device__ float g_norm[NUM_NODES];
__device__ float g_deg[NUM_NODES];

// ---------------------------------------------------------------------------
// 1) zero deg
__global__ void zero_deg_kernel(int n) {
    int i = blockIdx.x * blockDim.x + threadIdx.x;
    if (i < n) g_deg[i] = 0.0f;
}

// 2) degree histogram over srcs
__global__ void deg_kernel(const int* __restrict__ srcs, int E) {
    int e = blockIdx.x * blockDim.x + threadIdx.x;
    if (e < E) atomicAdd(&g_deg[srcs[e]], 1.0f);  // no return use -> REDG
}

// 3) transform: one warp per node. lane f computes (features[n] @ K)[:,f],
//    scaled by rsqrt(max(deg,1)). Kernels staged in smem [k][f] (f contiguous,
//    conflict-free). Feature row distributed across lanes, combined via shfl.
__global__ void transform_kernel(const float* __restrict__ features,
                                 const float* __restrict__ kernels,
                                 int N) {
    __shared__ float sk[F * F];
    for (int i = threadIdx.x; i < F * F; i += blockDim.x)
        sk[i] = kernels[i];
    __syncthreads();

    int gwarp = (blockIdx.x * blockDim.x + threadIdx.x) >> 5;
    int lane  = threadIdx.x & 31;
    if (gwarp >= N) return;

    float feat = features[gwarp * F + lane];
    float acc = 0.0f;
#pragma unroll
    for (int k = 0; k < F; ++k)
        acc = fmaf(__shfl_sync(0xffffffffu, feat, k), sk[k * F + lane], acc);

    float nrm = rsqrtf(fmaxf(g_deg[gwarp], 1.0f));
    g_h[gwarp * F + lane] = acc * nrm;
    if (lane == 0) g_norm[gwarp] = nrm;
}

// 4) edge scatter: 8 threads per edge, one float4 chunk per thread.
//    Gather h'[dst] (L2-resident), scale by ew, vector-RED into out[src].
__global__ void edge_kernel(const int* __restrict__ srcs,
                            const int* __restrict__ dsts,
                            const float* __restrict__ ew,
                            float* __restrict__ out,
                            int E) {
    int t = blockIdx.x * blockDim.x + threadIdx.x;
    int e = t >> 3;
    int c = t & 7;
    if (e >= E) return;

    int s = __ldg(srcs + e);
    int d = __ldg(dsts + e);
    float w = __ldg(ew + e);

    const float4* hp = reinterpret_cast<const float4*>(g_h) + (size_t)d * 8 + c;
    float4 v = __ldg(hp);

    float4* op = reinterpret_cast<float4*>(out) + (size_t)s * 8 + c;
    asm volatile(
        "red.global.add.v4.f32 [%0], {%1, %2, %3, %4};"
        :: "l"(op), "f"(v.x * w), "f"(v.y * w), "f"(v.z * w), "f"(v.w * w)
        : "memory");
}

// 5) final scale + bias: out[n][f] = out[n][f]*norm[n] + bias[f]
__global__ void finalize_kernel(float* __restrict__ out,
                                const float* __restrict__ biases,
                                int total) {
    int i = blockIdx.x * blockDim.x + threadIdx.x;
    if (i < total) {
        int n = i >> 5;
        int f = i & 31;
        out[i] = out[i] * g_norm[n] + biases[f];
    }
}

extern "C" void kernel_launch(void* const* d_in, const int* in_sizes, int n_in,
                              void* d_out, int out_size) {
    const float* features = (const float*)d_in[0];
    const int*   srcs     = (const int*)d_in[1];
    const int*   dsts     = (const int*)d_in[2];
    const float* ew       = (const float*)d_in[3];
    const float* kernels  = (const float*)d_in[4];
    const float* biases   = (const float*)d_in[5];
    float*       out      = (float*)d_out;

    int N = in_sizes[0] / F;      // 100000
    int E = in_sizes[1];          // 3200000

    // out is poisoned; atomics need zeros.
    cudaMemsetAsync(d_out, 0, (size_t)out_size * sizeof(float));

    {
        int threads = 256;
        zero_deg_kernel<<<(N + threads - 1) / threads, threads>>>(N);
    }
    {
        int threads = 256;
        deg_kernel<<<(E + threads - 1) / threads, threads>>>(srcs, E);
    }
    {
        int threads = 256;                 // 8 warps = 8 nodes per block
        int nodes_per_block = threads / 32;
        int blocks = (N + nodes_per_block - 1) / nodes_per_block;
        transform_kernel<<<blocks, threads>>>(features, kernels, N);
    }
    {
        int threads = 256;                 // 32 edges per block (8 thr/edge)
        long long total = (long long)E * 8;
        int blocks = (int)((total + threads - 1) / threads);
        edge_kernel<<<blocks, threads>>>(srcs, dsts, ew, out, E);
    }
    {
        int threads = 256;
        int total = N * F;
        finalize_kernel<<<(total + threads - 1) / threads, threads>>>(out, biases, total);
    }
}